// round 9
// baseline (speedup 1.0000x reference)
#include <cuda_runtime.h>

// Problem constants: B=32, H=8, E=64, L=1024, MODES=64, OUT/8=64
#define BHN 256           // B*H
typedef unsigned long long u64;

// Scratch (allocation-free: device globals).
__device__ float2 g_Xq[BHN * 4096];
__device__ float2 g_Xk[BHN * 4096];
__device__ float2 g_Xqkv[BHN * 4096];
__device__ float2 g_Xw[BHN * 4096];

// ---- packed f32x2 helpers (Blackwell FFMA2 path) ----
__device__ __forceinline__ u64 pk2(float lo, float hi) {
    u64 r; asm("mov.b64 %0,{%1,%2};" : "=l"(r) : "f"(lo), "f"(hi)); return r;
}
__device__ __forceinline__ float2 upk2(u64 v) {
    float2 r; asm("mov.b64 {%0,%1},%2;" : "=f"(r.x), "=f"(r.y) : "l"(v)); return r;
}
__device__ __forceinline__ u64 ffma2(u64 a, u64 b, u64 c) {
    u64 d; asm("fma.rn.f32x2 %0,%1,%2,%3;" : "=l"(d) : "l"(a), "l"(b), "l"(c)); return d;
}
__device__ __forceinline__ u64 fadd2(u64 a, u64 b) {
    u64 d; asm("add.rn.f32x2 %0,%1,%2;" : "=l"(d) : "l"(a), "l"(b)); return d;
}

// ============================================================================
// K1: pruned rDFT, radix-2 decimation. Retiled 8e x 2m per thread with
// pre-DUPLICATED u64 smem operands: x values stored as (v,v) so the FFMA2
// x operand comes straight from LDS (no per-l MOV duplication), and each
// twiddle LDS.64 feeds 8 FFMA2.
//   X[m] = sum_{l<512} y[l] w^{ml},  y = s (m even) / d (m odd)
// ============================================================================
__global__ __launch_bounds__(256) void k_dft(const float* __restrict__ qp,
                                             const float* __restrict__ kp)
{
    __shared__ float2 tw[1024];    // 8KB
    __shared__ u64 ss[32 * 64];    // dup'd s chunk [l][e]  16KB
    __shared__ u64 dd[32 * 64];    // dup'd d chunk [l][e]  16KB
    const int tid = threadIdx.x;
    const int bh = blockIdx.x;
    const int b = bh >> 3, h = bh & 7;
    const float* src = (blockIdx.y == 0 ? qp : kp) + (size_t)b * 524288 + h * 64;
    float2* dst = (blockIdx.y == 0 ? g_Xq : g_Xk) + (size_t)bh * 4096;

    for (int k0 = tid; k0 < 1024; k0 += 256) {
        float s, c;
        sincosf(-6.2831853071795864769f * (float)k0 * (1.0f / 1024.0f), &s, &c);
        tw[k0] = make_float2(c, s);
    }

    const int eg = tid & 7;        // e = eg*8 + i, i<8
    const int mg = tid >> 3;       // m = mg + 32*j, j<2 (parity(m)=parity(mg))
    const u64* yb = ((mg & 1) ? dd : ss) + eg * 8;

    // staging-loop invariants (hoisted): this thread writes rows l0=tid>>4
    // and l0+16, e-quad e4=tid&15.
    const int l0 = tid >> 4, e4 = tid & 15;
    u64* sp0 = &ss[l0 * 64 + e4 * 4];
    u64* dp0 = &dd[l0 * 64 + e4 * 4];

    u64 acc0[8], acc1[8];
#pragma unroll
    for (int i = 0; i < 8; i++) { acc0[i] = 0ULL; acc1[i] = 0ULL; }

    for (int c0 = 0; c0 < 16; c0++) {
        __syncthreads();
        // stage 32 l's worth of duplicated s/d values
#pragma unroll
        for (int t = 0; t < 2; t++) {
            int l = l0 + t * 16;
            size_t off = (size_t)(c0 * 32 + l) * 512 + e4 * 4;
            float4 a  = *(const float4*)(src + off);
            float4 b4 = *(const float4*)(src + off + 262144);   // l+512
            u64* sp = sp0 + t * 16 * 64;
            u64* dp = dp0 + t * 16 * 64;
            float v;
            v = a.x + b4.x; sp[0] = pk2(v, v);
            v = a.y + b4.y; sp[1] = pk2(v, v);
            v = a.z + b4.z; sp[2] = pk2(v, v);
            v = a.w + b4.w; sp[3] = pk2(v, v);
            v = a.x - b4.x; dp[0] = pk2(v, v);
            v = a.y - b4.y; dp[1] = pk2(v, v);
            v = a.z - b4.z; dp[2] = pk2(v, v);
            v = a.w - b4.w; dp[3] = pk2(v, v);
        }
        __syncthreads();

        u64 c0a[8], c1a[8];     // chunk accumulators (2-level sum: accuracy)
#pragma unroll
        for (int i = 0; i < 8; i++) { c0a[i] = 0ULL; c1a[i] = 0ULL; }

#pragma unroll 4
        for (int l = 0; l < 32; l++) {
            const int lg = c0 * 32 + l;
            u64 x[8];
#pragma unroll
            for (int i = 0; i < 8; i++) x[i] = yb[l * 64 + i];
            int kk0 = (mg * lg) & 1023;
            int kk1 = (kk0 + (lg << 5)) & 1023;
            u64 t0 = *(const u64*)&tw[kk0];
            u64 t1 = *(const u64*)&tw[kk1];
#pragma unroll
            for (int i = 0; i < 8; i++) {
                c0a[i] = ffma2(x[i], t0, c0a[i]);
                c1a[i] = ffma2(x[i], t1, c1a[i]);
            }
        }
#pragma unroll
        for (int i = 0; i < 8; i++) {
            acc0[i] = fadd2(acc0[i], c0a[i]);
            acc1[i] = fadd2(acc1[i], c1a[i]);
        }
    }

#pragma unroll
    for (int i = 0; i < 8; i++) {
        dst[(eg * 8 + i) * 64 + mg]      = upk2(acc0[i]);
        dst[(eg * 8 + i) * 64 + mg + 32] = upk2(acc1[i]);
    }
}

// ============================================================================
// K2 (fused qk + qkv):
//   phase 1: xqk[x,y] = sum_e Xq[e,x]*Xk[e,y]; complex tanh -> T (kept in smem)
//   phase 2: xqkv[e,x] = sum_y T[x,y]*Xk[e,y]
// smem: buf (32KB) unions phase-1 staging (Aq|Ak) with phase-2 Ts[64][64];
//       Bk staged in y-quarters (8.5KB). Total 40.7KB static.
// ============================================================================
__global__ __launch_bounds__(256) void k_qk2(void)
{
    __shared__ float2 buf[4096];     // phase1: Aq=buf[0..2047], Ak=buf[2048..]; phase2: Ts pitch 64
    __shared__ float2 Bk[64 * 17];   // [e][yy] pitch 17 (conflict-free strided reads)
    const int tid = threadIdx.x, bh = blockIdx.x;
    const float2* xq = g_Xq + (size_t)bh * 4096;
    const float2* xk = g_Xk + (size_t)bh * 4096;
    const int xg = tid & 15, yg = tid >> 4;

    float2 c[4][4];
#pragma unroll
    for (int i = 0; i < 4; i++)
#pragma unroll
        for (int j = 0; j < 4; j++) c[i][j] = make_float2(0.f, 0.f);

    for (int s = 0; s < 2; s++) {
        __syncthreads();
        for (int idx = tid; idx < 2048; idx += 256) {
            buf[idx]        = xq[s * 2048 + idx];
            buf[2048 + idx] = xk[s * 2048 + idx];
        }
        __syncthreads();
        for (int e = 0; e < 32; e++) {
            float4 a01 = *(const float4*)&buf[e * 64 + xg * 4];
            float4 a23 = *(const float4*)&buf[e * 64 + xg * 4 + 2];
            float4 b01 = *(const float4*)&buf[2048 + e * 64 + yg * 4];
            float4 b23 = *(const float4*)&buf[2048 + e * 64 + yg * 4 + 2];
            float2 aq[4] = { {a01.x,a01.y},{a01.z,a01.w},{a23.x,a23.y},{a23.z,a23.w} };
            float2 ak[4] = { {b01.x,b01.y},{b01.z,b01.w},{b23.x,b23.y},{b23.z,b23.w} };
#pragma unroll
            for (int i = 0; i < 4; i++)
#pragma unroll
                for (int j = 0; j < 4; j++) {
                    c[i][j].x += aq[i].x * ak[j].x;
                    c[i][j].x -= aq[i].y * ak[j].y;
                    c[i][j].y += aq[i].x * ak[j].y;
                    c[i][j].y += aq[i].y * ak[j].x;
                }
        }
    }

    // complex tanh into registers, then hand T across threads via smem
    float2 treg[4][4];
#pragma unroll
    for (int i = 0; i < 4; i++)
#pragma unroll
        for (int j = 0; j < 4; j++) {
            float t = tanhf(c[i][j].x);
            float u = tanf(c[i][j].y);
            float u2 = u * u;
            float rr, ii;
            if (!(u2 < 1e30f)) { rr = 1.0f / t; ii = 0.0f; }
            else {
                float inv = 1.0f / fmaf(t * t, u2, 1.0f);
                rr = t * (1.0f + u2) * inv;
                ii = u * (1.0f - t * t) * inv;
            }
            treg[i][j] = make_float2(rr, ii);
        }
    __syncthreads();                 // all phase-1 reads of buf done
#pragma unroll
    for (int i = 0; i < 4; i++)
#pragma unroll
        for (int j = 0; j < 4; j++)
            buf[(xg * 4 + i) * 64 + yg * 4 + j] = treg[i][j];   // Ts[x][y]

    // phase 2
    const int eg2 = tid & 15, xg2 = tid >> 4;   // e = eg2+16i, x = xg2*4+j
    float2 c2[4][4];
#pragma unroll
    for (int i = 0; i < 4; i++)
#pragma unroll
        for (int j = 0; j < 4; j++) c2[i][j] = make_float2(0.f, 0.f);

    for (int ys = 0; ys < 4; ys++) {
        __syncthreads();             // Ts ready (first iter) / prior Bk reads done
        for (int idx = tid; idx < 1024; idx += 256) {
            int r = idx >> 4, yy = idx & 15;
            Bk[r * 17 + yy] = xk[r * 64 + ys * 16 + yy];
        }
        __syncthreads();
        for (int y = 0; y < 16; y++) {
            float2 kv[4], tt[4];
#pragma unroll
            for (int i = 0; i < 4; i++) kv[i] = Bk[(eg2 + 16 * i) * 17 + y];
#pragma unroll
            for (int j = 0; j < 4; j++) tt[j] = buf[(xg2 * 4 + j) * 64 + ys * 16 + y];
#pragma unroll
            for (int i = 0; i < 4; i++)
#pragma unroll
                for (int j = 0; j < 4; j++) {
                    c2[i][j].x += tt[j].x * kv[i].x;
                    c2[i][j].x -= tt[j].y * kv[i].y;
                    c2[i][j].y += tt[j].x * kv[i].y;
                    c2[i][j].y += tt[j].y * kv[i].x;
                }
        }
    }
#pragma unroll
    for (int i = 0; i < 4; i++)
#pragma unroll
        for (int j = 0; j < 4; j++)
            g_Xqkv[(size_t)bh * 4096 + (eg2 + 16 * i) * 64 + (xg2 * 4 + j)] = c2[i][j];
}

// ============================================================================
// K4: xw[b,o,x] = sum_e xqkv[b,e,x] * (Wr+iWi)[h,e,o,x].
// block = (h, x-quarter, b-group of 4); W loads x-coalesced, reused 4x over b.
// Manual double-buffered W loads (e-pipelined) -> 16 LDGs in flight,
// hides L2 latency at the low (1.7 CTA/SM) occupancy this grid gives.
// ============================================================================
__global__ __launch_bounds__(256) void k_w(const float* __restrict__ Wr,
                                           const float* __restrict__ Wi)
{
    __shared__ float2 Xs[4][64][16];   // [bb][e][x16]  32KB
    const int tid = threadIdx.x;
    const int bx = blockIdx.x;
    const int h  = bx & 7;
    const int xq = (bx >> 3) & 3;      // x-quarter
    const int bq = bx >> 5;            // b-group of 4 (8 groups)

    for (int idx = tid; idx < 4096; idx += 256) {
        int bb = idx >> 10, rem = idx & 1023;
        int e = rem >> 4, xx = rem & 15;
        int b = bq * 4 + bb;
        Xs[bb][e][xx] = g_Xqkv[(size_t)(b * 8 + h) * 4096 + e * 64 + xq * 16 + xx];
    }
    __syncthreads();

    const int x  = tid & 15;           // mode (lane-contiguous -> coalesced W)
    const int og = tid >> 4;           // o = og*4 + i

    u64 acc[4][4];                     // [bb][i]
#pragma unroll
    for (int bb = 0; bb < 4; bb++)
#pragma unroll
        for (int i = 0; i < 4; i++) acc[bb][i] = 0ULL;

    const size_t base = ((size_t)(h * 64) * 64 + og * 4) * 64 + xq * 16 + x;
    u64 wa[2][4], wb[2][4];
#pragma unroll
    for (int i = 0; i < 4; i++) {       // prologue: e=0
        float wr = __ldg(Wr + base + i * 64);
        float wi = __ldg(Wi + base + i * 64);
        wa[0][i] = pk2(wr, wi); wb[0][i] = pk2(wi, wr);
    }

    for (int e = 0; e < 64; e += 2) {
        // prefetch e+1 into buffer 1
        size_t b1 = base + (size_t)(e + 1) * 4096;
#pragma unroll
        for (int i = 0; i < 4; i++) {
            float wr = __ldg(Wr + b1 + i * 64);
            float wi = __ldg(Wi + b1 + i * 64);
            wa[1][i] = pk2(wr, wi); wb[1][i] = pk2(wi, wr);
        }
        // compute with e (buffer 0)
#pragma unroll
        for (int bb = 0; bb < 4; bb++) {
            float2 xv = Xs[bb][e][x];
            u64 xr = pk2(xv.x, xv.x);
            u64 xm = pk2(-xv.y, xv.y);
#pragma unroll
            for (int i = 0; i < 4; i++) {
                acc[bb][i] = ffma2(xr, wa[0][i], acc[bb][i]);
                acc[bb][i] = ffma2(xm, wb[0][i], acc[bb][i]);
            }
        }
        // prefetch e+2 into buffer 0
        if (e + 2 < 64) {
            size_t b2 = base + (size_t)(e + 2) * 4096;
#pragma unroll
            for (int i = 0; i < 4; i++) {
                float wr = __ldg(Wr + b2 + i * 64);
                float wi = __ldg(Wi + b2 + i * 64);
                wa[0][i] = pk2(wr, wi); wb[0][i] = pk2(wi, wr);
            }
        }
        // compute with e+1 (buffer 1)
#pragma unroll
        for (int bb = 0; bb < 4; bb++) {
            float2 xv = Xs[bb][e + 1][x];
            u64 xr = pk2(xv.x, xv.x);
            u64 xm = pk2(-xv.y, xv.y);
#pragma unroll
            for (int i = 0; i < 4; i++) {
                acc[bb][i] = ffma2(xr, wa[1][i], acc[bb][i]);
                acc[bb][i] = ffma2(xm, wb[1][i], acc[bb][i]);
            }
        }
    }

#pragma unroll
    for (int bb = 0; bb < 4; bb++)
#pragma unroll
        for (int i = 0; i < 4; i++)
            g_Xw[(size_t)((bq * 4 + bb) * 8 + h) * 4096 + (og * 4 + i) * 64 + xq * 16 + x]
                = upk2(acc[bb][i]);
}

// ============================================================================
// K5: pruned irfft, radix-2 on the output. E/O mode pairs loaded via one
// LDS.128 (pitch 66 keeps 16B alignment). Grid split to 512 CTAs (2 per bh,
// each doing half the n-range) for better wave balance.
// ============================================================================
__global__ __launch_bounds__(256) void k_irfft(float* __restrict__ out)
{
    __shared__ float2 Xs[64 * 66];   // [o][m] pitch 66 (even -> 16B-aligned pairs)
    __shared__ float2 tw[1024];      // (cos, sin)(2pi k/1024)
    const int tid = threadIdx.x;
    const int bh = blockIdx.x >> 1, half = blockIdx.x & 1;
    for (int k0 = tid; k0 < 1024; k0 += 256) {
        float s, c;
        sincosf(6.2831853071795864769f * (float)k0 * (1.0f / 1024.0f), &s, &c);
        tw[k0] = make_float2(c, s);
    }
    const float2* src = g_Xw + (size_t)bh * 4096;
    const float S1 = 1.0f / 268435456.0f;   // 2^-28
    for (int idx = tid; idx < 4096; idx += 256) {
        int o = idx >> 6, m = idx & 63;
        float2 v = src[idx];
        float sc = (m == 0) ? S1 : 2.0f * S1;
        Xs[o * 66 + m] = make_float2(v.x * sc, -v.y * sc);
    }
    __syncthreads();

    const int og = tid & 15;   // o = og + 16*i
    const int ng = tid >> 4;   // n tile base (const per half-warp -> tw broadcast)
    float* obase = out + (size_t)bh * 65536;

    for (int nc = half * 4; nc < half * 4 + 4; nc++) {
        u64 accE[4][4], accO[4][4];
#pragma unroll
        for (int i = 0; i < 4; i++)
#pragma unroll
            for (int j = 0; j < 4; j++) { accE[i][j] = 0ULL; accO[i][j] = 0ULL; }
        const int n0 = nc * 64 + ng * 4;   // < 512
#pragma unroll 2
        for (int m = 0; m < 64; m += 2) {
            u64 xwE[4], xwO[4];
#pragma unroll
            for (int i = 0; i < 4; i++) {
                ulonglong2 v = *(const ulonglong2*)&Xs[(og + 16 * i) * 66 + m];
                xwE[i] = v.x; xwO[i] = v.y;
            }
            int kkE = (m * n0) & 1023;
            int kkO = ((m + 1) * n0) & 1023;
#pragma unroll
            for (int j = 0; j < 4; j++) {
                u64 tE = *(const u64*)&tw[kkE];
                u64 tO = *(const u64*)&tw[kkO];
                accE[0][j] = ffma2(xwE[0], tE, accE[0][j]);
                accE[1][j] = ffma2(xwE[1], tE, accE[1][j]);
                accE[2][j] = ffma2(xwE[2], tE, accE[2][j]);
                accE[3][j] = ffma2(xwE[3], tE, accE[3][j]);
                accO[0][j] = ffma2(xwO[0], tO, accO[0][j]);
                accO[1][j] = ffma2(xwO[1], tO, accO[1][j]);
                accO[2][j] = ffma2(xwO[2], tO, accO[2][j]);
                accO[3][j] = ffma2(xwO[3], tO, accO[3][j]);
                kkE = (kkE + m) & 1023;
                kkO = (kkO + m + 1) & 1023;
            }
        }
#pragma unroll
        for (int i = 0; i < 4; i++) {
            float4 rlo, rhi;
#pragma unroll
            for (int j = 0; j < 4; j++) {
                float2 ev = upk2(accE[i][j]);
                float2 ov = upk2(accO[i][j]);
                float e = ev.x + ev.y, o = ov.x + ov.y;
                ((float*)&rlo)[j] = e + o;
                ((float*)&rhi)[j] = e - o;
            }
            float* row = obase + (size_t)(og + 16 * i) * 1024;
            *(float4*)(row + n0)       = rlo;
            *(float4*)(row + n0 + 512) = rhi;
        }
    }
}

// ============================================================================
extern "C" void kernel_launch(void* const* d_in, const int* in_sizes, int n_in,
                              void* d_out, int out_size)
{
    const float* q  = (const float*)d_in[0];
    const float* k  = (const float*)d_in[1];
    // d_in[2] = v : unused by the reference math
    const float* Wr = (const float*)d_in[3];
    const float* Wi = (const float*)d_in[4];
    float* out = (float*)d_out;

    k_dft  <<<dim3(BHN, 2), 256>>>(q, k);
    k_qk2  <<<BHN, 256>>>();
    k_w    <<<BHN, 256>>>(Wr, Wi);
    k_irfft<<<BHN * 2, 256>>>(out);
}

// round 10
// speedup vs baseline: 2.2929x; 2.2929x over previous
#include <cuda_runtime.h>

// Problem constants: B=32, H=8, E=64, L=1024, MODES=64, OUT/8=64
#define BHN 256           // B*H
typedef unsigned long long u64;

// Scratch (allocation-free: device globals).
__device__ float2 g_Xq[BHN * 4096];
__device__ float2 g_Xk[BHN * 4096];
__device__ float2 g_T [BHN * 4096];
__device__ float2 g_Xqkv[BHN * 4096];
__device__ float2 g_Xw[BHN * 4096];

// ---- packed f32x2 helpers (Blackwell FFMA2 path) ----
__device__ __forceinline__ u64 pk2(float lo, float hi) {
    u64 r; asm("mov.b64 %0,{%1,%2};" : "=l"(r) : "f"(lo), "f"(hi)); return r;
}
__device__ __forceinline__ float2 upk2(u64 v) {
    float2 r; asm("mov.b64 {%0,%1},%2;" : "=f"(r.x), "=f"(r.y) : "l"(v)); return r;
}
__device__ __forceinline__ u64 ffma2(u64 a, u64 b, u64 c) {
    u64 d; asm("fma.rn.f32x2 %0,%1,%2,%3;" : "=l"(d) : "l"(a), "l"(b), "l"(c)); return d;
}
__device__ __forceinline__ u64 fadd2(u64 a, u64 b) {
    u64 d; asm("add.rn.f32x2 %0,%1,%2;" : "=l"(d) : "l"(a), "l"(b)); return d;
}

// ============================================================================
// K1: pruned rDFT, radix-2 decimation (Round-5 proven version):
//   X[m] = sum_{l<512} y[l] w^{ml},  y = s (m even) / d (m odd),
//   s[l] = x[l]+x[l+512], d[l] = x[l]-x[l+512]   (w^{512m} = (-1)^m)
// grid (256,2): y=0 -> q, y=1 -> k. 256 threads, thread tile 4e x 4m.
// ============================================================================
__global__ __launch_bounds__(256) void k_dft(const float* __restrict__ qp,
                                             const float* __restrict__ kp)
{
    __shared__ float2 tw[1024];    // e^{-2pi i k/1024}  (8KB)
    __shared__ float4 ss[1024];    // s chunk: [l 0..63][e-group 0..15] (16KB)
    __shared__ float4 dd[1024];    // d chunk (16KB)
    const int tid = threadIdx.x;
    const int bh = blockIdx.x;
    const int b = bh >> 3, h = bh & 7;
    const float* src = (blockIdx.y == 0 ? qp : kp) + (size_t)b * 524288 + h * 64;
    float2* dst = (blockIdx.y == 0 ? g_Xq : g_Xk) + (size_t)bh * 4096;

    for (int k0 = tid; k0 < 1024; k0 += 256) {
        float s, c;
        sincosf(-6.2831853071795864769f * (float)k0 * (1.0f / 1024.0f), &s, &c);
        tw[k0] = make_float2(c, s);
    }

    const int eg = tid & 15;       // e group: e = eg*4 + i   (varies per lane)
    const int mg = tid >> 4;       // m group: m = mg + 16*j  (const per half-warp)
    const float4* ybase = (mg & 1) ? dd : ss;   // parity(m) == parity(mg)

    u64 acc[4][4];
#pragma unroll
    for (int i = 0; i < 4; i++)
#pragma unroll
        for (int j = 0; j < 4; j++) acc[i][j] = 0ULL;

    for (int c0 = 0; c0 < 8; c0++) {
        __syncthreads();
        for (int idx = tid; idx < 1024; idx += 256) {
            int l = idx >> 4, e4 = idx & 15;
            size_t off = (size_t)(c0 * 64 + l) * 512 + e4 * 4;
            float4 a = *(const float4*)(src + off);
            float4 bb4 = *(const float4*)(src + off + 262144);  // l+512
            ss[idx] = make_float4(a.x + bb4.x, a.y + bb4.y, a.z + bb4.z, a.w + bb4.w);
            dd[idx] = make_float4(a.x - bb4.x, a.y - bb4.y, a.z - bb4.z, a.w - bb4.w);
        }
        __syncthreads();

        u64 cacc[4][4];   // chunk accumulators (2-level sum: fp32 accuracy)
#pragma unroll
        for (int i = 0; i < 4; i++)
#pragma unroll
            for (int j = 0; j < 4; j++) cacc[i][j] = 0ULL;

#pragma unroll 8
        for (int l = 0; l < 64; l++) {
            const int lg = c0 * 64 + l;
            float4 xv = ybase[l * 16 + eg];
            u64 x0 = pk2(xv.x, xv.x), x1 = pk2(xv.y, xv.y);
            u64 x2 = pk2(xv.z, xv.z), x3 = pk2(xv.w, xv.w);
            int kk = (mg * lg) & 1023;
            const int dk = (lg << 4) & 1023;
#pragma unroll
            for (int j = 0; j < 4; j++) {
                u64 t = *(const u64*)&tw[kk];
                cacc[0][j] = ffma2(x0, t, cacc[0][j]);
                cacc[1][j] = ffma2(x1, t, cacc[1][j]);
                cacc[2][j] = ffma2(x2, t, cacc[2][j]);
                cacc[3][j] = ffma2(x3, t, cacc[3][j]);
                kk = (kk + dk) & 1023;
            }
        }
#pragma unroll
        for (int i = 0; i < 4; i++)
#pragma unroll
            for (int j = 0; j < 4; j++) acc[i][j] = fadd2(acc[i][j], cacc[i][j]);
    }

#pragma unroll
    for (int i = 0; i < 4; i++)
#pragma unroll
        for (int j = 0; j < 4; j++)
            dst[(eg * 4 + i) * 64 + (mg + 16 * j)] = upk2(acc[i][j]);
}

// ============================================================================
// K2: xqk[x,y] = sum_e Xq[e,x]*Xk[e,y]  (complex, no conj), then complex tanh.
// ============================================================================
__global__ __launch_bounds__(256) void k_qk(void)
{
    __shared__ float2 Aq[32 * 64];   // [e-half][x]
    __shared__ float2 Ak[32 * 64];   // [e-half][y]
    const int tid = threadIdx.x, bh = blockIdx.x;
    const float2* xq = g_Xq + (size_t)bh * 4096;
    const float2* xk = g_Xk + (size_t)bh * 4096;
    const int xg = tid & 15, yg = tid >> 4;

    float2 c[4][4];
#pragma unroll
    for (int i = 0; i < 4; i++)
#pragma unroll
        for (int j = 0; j < 4; j++) c[i][j] = make_float2(0.f, 0.f);

    for (int s = 0; s < 2; s++) {
        __syncthreads();
        for (int idx = tid; idx < 2048; idx += 256) {
            Aq[idx] = xq[s * 2048 + idx];
            Ak[idx] = xk[s * 2048 + idx];
        }
        __syncthreads();
        for (int e = 0; e < 32; e++) {
            float4 a01 = *(const float4*)&Aq[e * 64 + xg * 4];
            float4 a23 = *(const float4*)&Aq[e * 64 + xg * 4 + 2];
            float4 b01 = *(const float4*)&Ak[e * 64 + yg * 4];
            float4 b23 = *(const float4*)&Ak[e * 64 + yg * 4 + 2];
            float2 aq[4] = { {a01.x,a01.y},{a01.z,a01.w},{a23.x,a23.y},{a23.z,a23.w} };
            float2 ak[4] = { {b01.x,b01.y},{b01.z,b01.w},{b23.x,b23.y},{b23.z,b23.w} };
#pragma unroll
            for (int i = 0; i < 4; i++)
#pragma unroll
                for (int j = 0; j < 4; j++) {
                    c[i][j].x += aq[i].x * ak[j].x;
                    c[i][j].x -= aq[i].y * ak[j].y;
                    c[i][j].y += aq[i].x * ak[j].y;
                    c[i][j].y += aq[i].y * ak[j].x;
                }
        }
    }

#pragma unroll
    for (int i = 0; i < 4; i++)
#pragma unroll
        for (int j = 0; j < 4; j++) {
            // stable complex tanh: tanh(x+iy) = (t(1+u^2) + i u(1-t^2)) / (1 + t^2 u^2)
            float t = tanhf(c[i][j].x);
            float u = tanf(c[i][j].y);
            float u2 = u * u;
            float rr, ii;
            if (!(u2 < 1e30f)) { rr = 1.0f / t; ii = 0.0f; }
            else {
                float inv = 1.0f / fmaf(t * t, u2, 1.0f);
                rr = t * (1.0f + u2) * inv;
                ii = u * (1.0f - t * t) * inv;
            }
            g_T[(size_t)bh * 4096 + (xg * 4 + i) * 64 + (yg * 4 + j)] = make_float2(rr, ii);
        }
}

// ============================================================================
// K3: xqkv[e,x] = sum_y T[x,y]*Xk[e,y]. y staged in halves; Bk padded pitch 33.
// ============================================================================
__global__ __launch_bounds__(256) void k_qkv(void)
{
    __shared__ float2 Tt[64 * 32];   // [x][yy] pitch 32
    __shared__ float2 Bk[64 * 33];   // [e][yy] pitch 33 (conflict-free strided reads)
    const int tid = threadIdx.x, bh = blockIdx.x;
    const float2* tp = g_T + (size_t)bh * 4096;
    const float2* kp = g_Xk + (size_t)bh * 4096;
    const int eg = tid & 15, xg = tid >> 4;   // e = eg+16i (per-lane), x = xg*4+j

    float2 c[4][4];
#pragma unroll
    for (int i = 0; i < 4; i++)
#pragma unroll
        for (int j = 0; j < 4; j++) c[i][j] = make_float2(0.f, 0.f);

    for (int s = 0; s < 2; s++) {
        __syncthreads();
        for (int idx = tid; idx < 2048; idx += 256) {
            int r = idx >> 5, yy = idx & 31;
            Tt[r * 32 + yy] = tp[r * 64 + s * 32 + yy];
            Bk[r * 33 + yy] = kp[r * 64 + s * 32 + yy];
        }
        __syncthreads();
        for (int y = 0; y < 32; y++) {
            float2 kv[4], tt[4];
#pragma unroll
            for (int i = 0; i < 4; i++) kv[i] = Bk[(eg + 16 * i) * 33 + y];
#pragma unroll
            for (int j = 0; j < 4; j++) tt[j] = Tt[(xg * 4 + j) * 32 + y];
#pragma unroll
            for (int i = 0; i < 4; i++)
#pragma unroll
                for (int j = 0; j < 4; j++) {
                    c[i][j].x += tt[j].x * kv[i].x;
                    c[i][j].x -= tt[j].y * kv[i].y;
                    c[i][j].y += tt[j].x * kv[i].y;
                    c[i][j].y += tt[j].y * kv[i].x;
                }
        }
    }
#pragma unroll
    for (int i = 0; i < 4; i++)
#pragma unroll
        for (int j = 0; j < 4; j++)
            g_Xqkv[(size_t)bh * 4096 + (eg + 16 * i) * 64 + (xg * 4 + j)] = c[i][j];
}

// ============================================================================
// K4: xw[b,o,x] = sum_e xqkv[b,e,x] * (Wr+iWi)[h,e,o,x].
// block = (h, x-quarter, b-group of 4); W loads x-coalesced, reused 4x over b.
// THE ONE CHANGE THIS ROUND: manual double-buffered W loads (e-pipelined)
// -> 16 LDGs in flight, hides L2 latency at the ~1.7 CTA/SM occupancy.
// ============================================================================
__global__ __launch_bounds__(256) void k_w(const float* __restrict__ Wr,
                                           const float* __restrict__ Wi)
{
    __shared__ float2 Xs[4][64][16];   // [bb][e][x16]  32KB
    const int tid = threadIdx.x;
    const int bx = blockIdx.x;
    const int h  = bx & 7;
    const int xq = (bx >> 3) & 3;      // x-quarter
    const int bq = bx >> 5;            // b-group of 4 (8 groups)

    for (int idx = tid; idx < 4096; idx += 256) {
        int bb = idx >> 10, rem = idx & 1023;
        int e = rem >> 4, xx = rem & 15;
        int b = bq * 4 + bb;
        Xs[bb][e][xx] = g_Xqkv[(size_t)(b * 8 + h) * 4096 + e * 64 + xq * 16 + xx];
    }
    __syncthreads();

    const int x  = tid & 15;           // mode (lane-contiguous -> coalesced W)
    const int og = tid >> 4;           // o = og*4 + i

    u64 acc[4][4];                     // [bb][i]
#pragma unroll
    for (int bb = 0; bb < 4; bb++)
#pragma unroll
        for (int i = 0; i < 4; i++) acc[bb][i] = 0ULL;

    const size_t base = ((size_t)(h * 64) * 64 + og * 4) * 64 + xq * 16 + x;
    u64 wa[2][4], wb[2][4];
#pragma unroll
    for (int i = 0; i < 4; i++) {       // prologue: e=0
        float wr = __ldg(Wr + base + i * 64);
        float wi = __ldg(Wi + base + i * 64);
        wa[0][i] = pk2(wr, wi); wb[0][i] = pk2(wi, wr);
    }

    for (int e = 0; e < 64; e += 2) {
        // prefetch e+1 into buffer 1
        size_t b1 = base + (size_t)(e + 1) * 4096;
#pragma unroll
        for (int i = 0; i < 4; i++) {
            float wr = __ldg(Wr + b1 + i * 64);
            float wi = __ldg(Wi + b1 + i * 64);
            wa[1][i] = pk2(wr, wi); wb[1][i] = pk2(wi, wr);
        }
        // compute with e (buffer 0)
#pragma unroll
        for (int bb = 0; bb < 4; bb++) {
            float2 xv = Xs[bb][e][x];
            u64 xr = pk2(xv.x, xv.x);
            u64 xm = pk2(-xv.y, xv.y);
#pragma unroll
            for (int i = 0; i < 4; i++) {
                acc[bb][i] = ffma2(xr, wa[0][i], acc[bb][i]);
                acc[bb][i] = ffma2(xm, wb[0][i], acc[bb][i]);
            }
        }
        // prefetch e+2 into buffer 0
        if (e + 2 < 64) {
            size_t b2 = base + (size_t)(e + 2) * 4096;
#pragma unroll
            for (int i = 0; i < 4; i++) {
                float wr = __ldg(Wr + b2 + i * 64);
                float wi = __ldg(Wi + b2 + i * 64);
                wa[0][i] = pk2(wr, wi); wb[0][i] = pk2(wi, wr);
            }
        }
        // compute with e+1 (buffer 1)
#pragma unroll
        for (int bb = 0; bb < 4; bb++) {
            float2 xv = Xs[bb][e + 1][x];
            u64 xr = pk2(xv.x, xv.x);
            u64 xm = pk2(-xv.y, xv.y);
#pragma unroll
            for (int i = 0; i < 4; i++) {
                acc[bb][i] = ffma2(xr, wa[1][i], acc[bb][i]);
                acc[bb][i] = ffma2(xm, wb[1][i], acc[bb][i]);
            }
        }
    }

#pragma unroll
    for (int bb = 0; bb < 4; bb++)
#pragma unroll
        for (int i = 0; i < 4; i++)
            g_Xw[(size_t)((bq * 4 + bb) * 8 + h) * 4096 + (og * 4 + i) * 64 + xq * 16 + x]
                = upk2(acc[bb][i]);
}

// ============================================================================
// K5: pruned irfft, radix-2 on the output (Round-5 proven version, pitch 65
// = conflict-free: bank stride 2*og, all 16 distinct).
//   out[n] = E(n)+O(n), out[n+512] = E(n)-O(n).  S1 = 2^-28.
// ============================================================================
__global__ __launch_bounds__(256) void k_irfft(float* __restrict__ out)
{
    __shared__ float2 Xs[64 * 65];   // [o][m], pitch 65 -> conflict-free
    __shared__ float2 tw[1024];      // (cos, sin)(2pi k/1024)
    const int tid = threadIdx.x, bh = blockIdx.x;
    for (int k0 = tid; k0 < 1024; k0 += 256) {
        float s, c;
        sincosf(6.2831853071795864769f * (float)k0 * (1.0f / 1024.0f), &s, &c);
        tw[k0] = make_float2(c, s);
    }
    const float2* src = g_Xw + (size_t)bh * 4096;
    const float S1 = 1.0f / 268435456.0f;   // 2^-28
    for (int idx = tid; idx < 4096; idx += 256) {
        int o = idx >> 6, m = idx & 63;
        float2 v = src[idx];
        float sc = (m == 0) ? S1 : 2.0f * S1;
        Xs[o * 65 + m] = make_float2(v.x * sc, -v.y * sc);
    }
    __syncthreads();

    const int og = tid & 15;   // o = og + 16*i
    const int ng = tid >> 4;   // n tile base (const per half-warp -> tw broadcast)
    float* obase = out + (size_t)bh * 65536;

    for (int nc = 0; nc < 8; nc++) {
        u64 accE[4][4], accO[4][4];
#pragma unroll
        for (int i = 0; i < 4; i++)
#pragma unroll
            for (int j = 0; j < 4; j++) { accE[i][j] = 0ULL; accO[i][j] = 0ULL; }
        const int n0 = nc * 64 + ng * 4;   // < 512
#pragma unroll 2
        for (int m = 0; m < 64; m += 2) {
            u64 xwE[4], xwO[4];
#pragma unroll
            for (int i = 0; i < 4; i++) {
                xwE[i] = *(const u64*)&Xs[(og + 16 * i) * 65 + m];
                xwO[i] = *(const u64*)&Xs[(og + 16 * i) * 65 + m + 1];
            }
            int kkE = (m * n0) & 1023;
            int kkO = ((m + 1) * n0) & 1023;
#pragma unroll
            for (int j = 0; j < 4; j++) {
                u64 tE = *(const u64*)&tw[kkE];
                u64 tO = *(const u64*)&tw[kkO];
                accE[0][j] = ffma2(xwE[0], tE, accE[0][j]);
                accE[1][j] = ffma2(xwE[1], tE, accE[1][j]);
                accE[2][j] = ffma2(xwE[2], tE, accE[2][j]);
                accE[3][j] = ffma2(xwE[3], tE, accE[3][j]);
                accO[0][j] = ffma2(xwO[0], tO, accO[0][j]);
                accO[1][j] = ffma2(xwO[1], tO, accO[1][j]);
                accO[2][j] = ffma2(xwO[2], tO, accO[2][j]);
                accO[3][j] = ffma2(xwO[3], tO, accO[3][j]);
                kkE = (kkE + m) & 1023;
                kkO = (kkO + m + 1) & 1023;
            }
        }
#pragma unroll
        for (int i = 0; i < 4; i++) {
            float4 rlo, rhi;
#pragma unroll
            for (int j = 0; j < 4; j++) {
                float2 ev = upk2(accE[i][j]);
                float2 ov = upk2(accO[i][j]);
                float e = ev.x + ev.y, o = ov.x + ov.y;
                ((float*)&rlo)[j] = e + o;
                ((float*)&rhi)[j] = e - o;
            }
            float* row = obase + (size_t)(og + 16 * i) * 1024;
            *(float4*)(row + n0)       = rlo;
            *(float4*)(row + n0 + 512) = rhi;
        }
    }
}

// ============================================================================
extern "C" void kernel_launch(void* const* d_in, const int* in_sizes, int n_in,
                              void* d_out, int out_size)
{
    const float* q  = (const float*)d_in[0];
    const float* k  = (const float*)d_in[1];
    // d_in[2] = v : unused by the reference math
    const float* Wr = (const float*)d_in[3];
    const float* Wi = (const float*)d_in[4];
    float* out = (float*)d_out;

    k_dft  <<<dim3(BHN, 2), 256>>>(q, k);
    k_qk   <<<BHN, 256>>>();
    k_qkv  <<<BHN, 256>>>();
    k_w    <<<BHN, 256>>>(Wr, Wi);
    k_irfft<<<BHN, 256>>>(out);
}

// round 12
// speedup vs baseline: 2.3840x; 1.0397x over previous
#include <cuda_runtime.h>

// Problem constants: B=32, H=8, E=64, L=1024, MODES=64, OUT/8=64
#define BHN 256           // B*H
typedef unsigned long long u64;

// Scratch (allocation-free: device globals).
__device__ float2 g_Xq[BHN * 4096];
__device__ float2 g_Xk[BHN * 4096];
__device__ float2 g_Xqkv[BHN * 4096];
__device__ float2 g_Xw[BHN * 4096];

// ---- packed f32x2 helpers (Blackwell FFMA2 path) ----
__device__ __forceinline__ u64 pk2(float lo, float hi) {
    u64 r; asm("mov.b64 %0,{%1,%2};" : "=l"(r) : "f"(lo), "f"(hi)); return r;
}
__device__ __forceinline__ float2 upk2(u64 v) {
    float2 r; asm("mov.b64 {%0,%1},%2;" : "=f"(r.x), "=f"(r.y) : "l"(v)); return r;
}
__device__ __forceinline__ u64 ffma2(u64 a, u64 b, u64 c) {
    u64 d; asm("fma.rn.f32x2 %0,%1,%2,%3;" : "=l"(d) : "l"(a), "l"(b), "l"(c)); return d;
}
__device__ __forceinline__ u64 fadd2(u64 a, u64 b) {
    u64 d; asm("add.rn.f32x2 %0,%1,%2;" : "=l"(d) : "l"(a), "l"(b)); return d;
}

// ============================================================================
// K1: pruned rDFT, radix-2 decimation (proven version, UNCHANGED):
//   X[m] = sum_{l<512} y[l] w^{ml},  y = s (m even) / d (m odd)
// ============================================================================
__global__ __launch_bounds__(256) void k_dft(const float* __restrict__ qp,
                                             const float* __restrict__ kp)
{
    __shared__ float2 tw[1024];    // e^{-2pi i k/1024}  (8KB)
    __shared__ float4 ss[1024];    // s chunk: [l 0..63][e-group 0..15] (16KB)
    __shared__ float4 dd[1024];    // d chunk (16KB)
    const int tid = threadIdx.x;
    const int bh = blockIdx.x;
    const int b = bh >> 3, h = bh & 7;
    const float* src = (blockIdx.y == 0 ? qp : kp) + (size_t)b * 524288 + h * 64;
    float2* dst = (blockIdx.y == 0 ? g_Xq : g_Xk) + (size_t)bh * 4096;

    for (int k0 = tid; k0 < 1024; k0 += 256) {
        float s, c;
        sincosf(-6.2831853071795864769f * (float)k0 * (1.0f / 1024.0f), &s, &c);
        tw[k0] = make_float2(c, s);
    }

    const int eg = tid & 15;       // e group: e = eg*4 + i   (varies per lane)
    const int mg = tid >> 4;       // m group: m = mg + 16*j  (const per half-warp)
    const float4* ybase = (mg & 1) ? dd : ss;   // parity(m) == parity(mg)

    u64 acc[4][4];
#pragma unroll
    for (int i = 0; i < 4; i++)
#pragma unroll
        for (int j = 0; j < 4; j++) acc[i][j] = 0ULL;

    for (int c0 = 0; c0 < 8; c0++) {
        __syncthreads();
        for (int idx = tid; idx < 1024; idx += 256) {
            int l = idx >> 4, e4 = idx & 15;
            size_t off = (size_t)(c0 * 64 + l) * 512 + e4 * 4;
            float4 a = *(const float4*)(src + off);
            float4 bb4 = *(const float4*)(src + off + 262144);  // l+512
            ss[idx] = make_float4(a.x + bb4.x, a.y + bb4.y, a.z + bb4.z, a.w + bb4.w);
            dd[idx] = make_float4(a.x - bb4.x, a.y - bb4.y, a.z - bb4.z, a.w - bb4.w);
        }
        __syncthreads();

        u64 cacc[4][4];   // chunk accumulators (2-level sum: fp32 accuracy)
#pragma unroll
        for (int i = 0; i < 4; i++)
#pragma unroll
            for (int j = 0; j < 4; j++) cacc[i][j] = 0ULL;

#pragma unroll 8
        for (int l = 0; l < 64; l++) {
            const int lg = c0 * 64 + l;
            float4 xv = ybase[l * 16 + eg];
            u64 x0 = pk2(xv.x, xv.x), x1 = pk2(xv.y, xv.y);
            u64 x2 = pk2(xv.z, xv.z), x3 = pk2(xv.w, xv.w);
            int kk = (mg * lg) & 1023;
            const int dk = (lg << 4) & 1023;
#pragma unroll
            for (int j = 0; j < 4; j++) {
                u64 t = *(const u64*)&tw[kk];
                cacc[0][j] = ffma2(x0, t, cacc[0][j]);
                cacc[1][j] = ffma2(x1, t, cacc[1][j]);
                cacc[2][j] = ffma2(x2, t, cacc[2][j]);
                cacc[3][j] = ffma2(x3, t, cacc[3][j]);
                kk = (kk + dk) & 1023;
            }
        }
#pragma unroll
        for (int i = 0; i < 4; i++)
#pragma unroll
            for (int j = 0; j < 4; j++) acc[i][j] = fadd2(acc[i][j], cacc[i][j]);
    }

#pragma unroll
    for (int i = 0; i < 4; i++)
#pragma unroll
        for (int j = 0; j < 4; j++)
            dst[(eg * 4 + i) * 64 + (mg + 16 * j)] = upk2(acc[i][j]);
}

// ============================================================================
// K2 (fused qk + qkv):
//   phase 1: xqk[x,y] = sum_e Xq[e,x]*Xk[e,y]; complex tanh -> T (kept in smem)
//   phase 2: xqkv[e,x] = sum_y T[x,y]*Xk[e,y]
// smem: buf (32KB) unions phase-1 staging (Aq|Ak) with phase-2 Ts[64][64];
//       Bk staged in y-quarters pitch 17 (conflict-free). 40.7KB static total.
// ============================================================================
__global__ __launch_bounds__(256) void k_qk2(void)
{
    __shared__ float2 buf[4096];     // phase1: Aq|Ak; phase2: Ts pitch 64
    __shared__ float2 Bk[64 * 17];   // [e][yy] pitch 17
    const int tid = threadIdx.x, bh = blockIdx.x;
    const float2* xq = g_Xq + (size_t)bh * 4096;
    const float2* xk = g_Xk + (size_t)bh * 4096;
    const int xg = tid & 15, yg = tid >> 4;

    float2 c[4][4];
#pragma unroll
    for (int i = 0; i < 4; i++)
#pragma unroll
        for (int j = 0; j < 4; j++) c[i][j] = make_float2(0.f, 0.f);

    for (int s = 0; s < 2; s++) {
        __syncthreads();
        for (int idx = tid; idx < 2048; idx += 256) {
            buf[idx]        = xq[s * 2048 + idx];
            buf[2048 + idx] = xk[s * 2048 + idx];
        }
        __syncthreads();
        for (int e = 0; e < 32; e++) {
            float4 a01 = *(const float4*)&buf[e * 64 + xg * 4];
            float4 a23 = *(const float4*)&buf[e * 64 + xg * 4 + 2];
            float4 b01 = *(const float4*)&buf[2048 + e * 64 + yg * 4];
            float4 b23 = *(const float4*)&buf[2048 + e * 64 + yg * 4 + 2];
            float2 aq[4] = { {a01.x,a01.y},{a01.z,a01.w},{a23.x,a23.y},{a23.z,a23.w} };
            float2 ak[4] = { {b01.x,b01.y},{b01.z,b01.w},{b23.x,b23.y},{b23.z,b23.w} };
#pragma unroll
            for (int i = 0; i < 4; i++)
#pragma unroll
                for (int j = 0; j < 4; j++) {
                    c[i][j].x += aq[i].x * ak[j].x;
                    c[i][j].x -= aq[i].y * ak[j].y;
                    c[i][j].y += aq[i].x * ak[j].y;
                    c[i][j].y += aq[i].y * ak[j].x;
                }
        }
    }

    // complex tanh into registers, then hand T across threads via smem
    float2 treg[4][4];
#pragma unroll
    for (int i = 0; i < 4; i++)
#pragma unroll
        for (int j = 0; j < 4; j++) {
            float t = tanhf(c[i][j].x);
            float u = tanf(c[i][j].y);
            float u2 = u * u;
            float rr, ii;
            if (!(u2 < 1e30f)) { rr = 1.0f / t; ii = 0.0f; }
            else {
                float inv = 1.0f / fmaf(t * t, u2, 1.0f);
                rr = t * (1.0f + u2) * inv;
                ii = u * (1.0f - t * t) * inv;
            }
            treg[i][j] = make_float2(rr, ii);
        }
    __syncthreads();                 // all phase-1 reads of buf done
#pragma unroll
    for (int i = 0; i < 4; i++)
#pragma unroll
        for (int j = 0; j < 4; j++)
            buf[(xg * 4 + i) * 64 + yg * 4 + j] = treg[i][j];   // Ts[x][y]

    // phase 2
    const int eg2 = tid & 15, xg2 = tid >> 4;   // e = eg2+16i, x = xg2*4+j
    float2 c2[4][4];
#pragma unroll
    for (int i = 0; i < 4; i++)
#pragma unroll
        for (int j = 0; j < 4; j++) c2[i][j] = make_float2(0.f, 0.f);

    for (int ys = 0; ys < 4; ys++) {
        __syncthreads();             // Ts ready (first iter) / prior Bk reads done
        for (int idx = tid; idx < 1024; idx += 256) {
            int r = idx >> 4, yy = idx & 15;
            Bk[r * 17 + yy] = xk[r * 64 + ys * 16 + yy];
        }
        __syncthreads();
        for (int y = 0; y < 16; y++) {
            float2 kv[4], tt[4];
#pragma unroll
            for (int i = 0; i < 4; i++) kv[i] = Bk[(eg2 + 16 * i) * 17 + y];
#pragma unroll
            for (int j = 0; j < 4; j++) tt[j] = buf[(xg2 * 4 + j) * 64 + ys * 16 + y];
#pragma unroll
            for (int i = 0; i < 4; i++)
#pragma unroll
                for (int j = 0; j < 4; j++) {
                    c2[i][j].x += tt[j].x * kv[i].x;
                    c2[i][j].x -= tt[j].y * kv[i].y;
                    c2[i][j].y += tt[j].x * kv[i].y;
                    c2[i][j].y += tt[j].y * kv[i].x;
                }
        }
    }
#pragma unroll
    for (int i = 0; i < 4; i++)
#pragma unroll
        for (int j = 0; j < 4; j++)
            g_Xqkv[(size_t)bh * 4096 + (eg2 + 16 * i) * 64 + (xg2 * 4 + j)] = c2[i][j];
}

// ============================================================================
// K4: xw[b,o,x] = sum_e xqkv[b,e,x] * (Wr+iWi)[h,e,o,x].
// NEW: o-range split across 2 CTAs (grid 256->512). Each block covers 32 o
// (thread tile 4bb x 2o): same total W/L2 traffic & smem, half the regs,
// double the CTAs/SM -> cures the grid-limited 20.7% occupancy.
// Double-buffered W prefetch retained.
// ============================================================================
__global__ __launch_bounds__(256) void k_w(const float* __restrict__ Wr,
                                           const float* __restrict__ Wi)
{
    __shared__ float2 Xs[4][64][16];   // [bb][e][x16]  32KB
    const int tid = threadIdx.x;
    const int bx = blockIdx.x;
    const int h  = bx & 7;
    const int xq = (bx >> 3) & 3;      // x-quarter
    const int oh = (bx >> 5) & 1;      // o-half
    const int bq = bx >> 6;            // b-group of 4 (8 groups)

    for (int idx = tid; idx < 4096; idx += 256) {
        int bb = idx >> 10, rem = idx & 1023;
        int e = rem >> 4, xx = rem & 15;
        int b = bq * 4 + bb;
        Xs[bb][e][xx] = g_Xqkv[(size_t)(b * 8 + h) * 4096 + e * 64 + xq * 16 + xx];
    }
    __syncthreads();

    const int x  = tid & 15;           // mode (lane-contiguous -> coalesced W)
    const int og = tid >> 4;           // o = oh*32 + og*2 + i, i<2

    u64 acc[4][2];                     // [bb][i]
#pragma unroll
    for (int bb = 0; bb < 4; bb++)
#pragma unroll
        for (int i = 0; i < 2; i++) acc[bb][i] = 0ULL;

    const size_t base = ((size_t)(h * 64) * 64 + oh * 32 + og * 2) * 64 + xq * 16 + x;
    u64 wa[2][2], wb[2][2];
#pragma unroll
    for (int i = 0; i < 2; i++) {       // prologue: e=0
        float wr = __ldg(Wr + base + i * 64);
        float wi = __ldg(Wi + base + i * 64);
        wa[0][i] = pk2(wr, wi); wb[0][i] = pk2(wi, wr);
    }

    for (int e = 0; e < 64; e += 2) {
        // prefetch e+1 into buffer 1
        size_t b1 = base + (size_t)(e + 1) * 4096;
#pragma unroll
        for (int i = 0; i < 2; i++) {
            float wr = __ldg(Wr + b1 + i * 64);
            float wi = __ldg(Wi + b1 + i * 64);
            wa[1][i] = pk2(wr, wi); wb[1][i] = pk2(wi, wr);
        }
        // compute with e (buffer 0)
#pragma unroll
        for (int bb = 0; bb < 4; bb++) {
            float2 xv = Xs[bb][e][x];
            u64 xr = pk2(xv.x, xv.x);
            u64 xm = pk2(-xv.y, xv.y);
#pragma unroll
            for (int i = 0; i < 2; i++) {
                acc[bb][i] = ffma2(xr, wa[0][i], acc[bb][i]);
                acc[bb][i] = ffma2(xm, wb[0][i], acc[bb][i]);
            }
        }
        // prefetch e+2 into buffer 0
        if (e + 2 < 64) {
            size_t b2 = base + (size_t)(e + 2) * 4096;
#pragma unroll
            for (int i = 0; i < 2; i++) {
                float wr = __ldg(Wr + b2 + i * 64);
                float wi = __ldg(Wi + b2 + i * 64);
                wa[0][i] = pk2(wr, wi); wb[0][i] = pk2(wi, wr);
            }
        }
        // compute with e+1 (buffer 1)
#pragma unroll
        for (int bb = 0; bb < 4; bb++) {
            float2 xv = Xs[bb][e + 1][x];
            u64 xr = pk2(xv.x, xv.x);
            u64 xm = pk2(-xv.y, xv.y);
#pragma unroll
            for (int i = 0; i < 2; i++) {
                acc[bb][i] = ffma2(xr, wa[1][i], acc[bb][i]);
                acc[bb][i] = ffma2(xm, wb[1][i], acc[bb][i]);
            }
        }
    }

#pragma unroll
    for (int bb = 0; bb < 4; bb++)
#pragma unroll
        for (int i = 0; i < 2; i++)
            g_Xw[(size_t)((bq * 4 + bb) * 8 + h) * 4096
                 + (oh * 32 + og * 2 + i) * 64 + xq * 16 + x] = upk2(acc[bb][i]);
}

// ============================================================================
// K5: pruned irfft, radix-2 on the output. Conflict-free pitch 65 KEPT.
// NEW: grid split x2 (512 CTAs, each does 4 nc chunks) -> cures grid-limited
// occupancy (was 1.7 CTA/SM).
//   out[n] = E(n)+O(n), out[n+512] = E(n)-O(n).  S1 = 2^-28.
// ============================================================================
__global__ __launch_bounds__(256) void k_irfft(float* __restrict__ out)
{
    __shared__ float2 Xs[64 * 65];   // [o][m], pitch 65 -> conflict-free
    __shared__ float2 tw[1024];      // (cos, sin)(2pi k/1024)
    const int tid = threadIdx.x;
    const int bh = blockIdx.x >> 1, half = blockIdx.x & 1;
    for (int k0 = tid; k0 < 1024; k0 += 256) {
        float s, c;
        sincosf(6.2831853071795864769f * (float)k0 * (1.0f / 1024.0f), &s, &c);
        tw[k0] = make_float2(c, s);
    }
    const float2* src = g_Xw + (size_t)bh * 4096;
    const float S1 = 1.0f / 268435456.0f;   // 2^-28
    for (int idx = tid; idx < 4096; idx += 256) {
        int o = idx >> 6, m = idx & 63;
        float2 v = src[idx];
        float sc = (m == 0) ? S1 : 2.0f * S1;
        Xs[o * 65 + m] = make_float2(v.x * sc, -v.y * sc);
    }
    __syncthreads();

    const int og = tid & 15;   // o = og + 16*i
    const int ng = tid >> 4;   // n tile base (const per half-warp -> tw broadcast)
    float* obase = out + (size_t)bh * 65536;

    for (int nc = half * 4; nc < half * 4 + 4; nc++) {
        u64 accE[4][4], accO[4][4];
#pragma unroll
        for (int i = 0; i < 4; i++)
#pragma unroll
            for (int j = 0; j < 4; j++) { accE[i][j] = 0ULL; accO[i][j] = 0ULL; }
        const int n0 = nc * 64 + ng * 4;   // < 512
#pragma unroll 2
        for (int m = 0; m < 64; m += 2) {
            u64 xwE[4], xwO[4];
#pragma unroll
            for (int i = 0; i < 4; i++) {
                xwE[i] = *(const u64*)&Xs[(og + 16 * i) * 65 + m];
                xwO[i] = *(const u64*)&Xs[(og + 16 * i) * 65 + m + 1];
            }
            int kkE = (m * n0) & 1023;
            int kkO = ((m + 1) * n0) & 1023;
#pragma unroll
            for (int j = 0; j < 4; j++) {
                u64 tE = *(const u64*)&tw[kkE];
                u64 tO = *(const u64*)&tw[kkO];
                accE[0][j] = ffma2(xwE[0], tE, accE[0][j]);
                accE[1][j] = ffma2(xwE[1], tE, accE[1][j]);
                accE[2][j] = ffma2(xwE[2], tE, accE[2][j]);
                accE[3][j] = ffma2(xwE[3], tE, accE[3][j]);
                accO[0][j] = ffma2(xwO[0], tO, accO[0][j]);
                accO[1][j] = ffma2(xwO[1], tO, accO[1][j]);
                accO[2][j] = ffma2(xwO[2], tO, accO[2][j]);
                accO[3][j] = ffma2(xwO[3], tO, accO[3][j]);
                kkE = (kkE + m) & 1023;
                kkO = (kkO + m + 1) & 1023;
            }
        }
#pragma unroll
        for (int i = 0; i < 4; i++) {
            float4 rlo, rhi;
#pragma unroll
            for (int j = 0; j < 4; j++) {
                float2 ev = upk2(accE[i][j]);
                float2 ov = upk2(accO[i][j]);
                float e = ev.x + ev.y, o = ov.x + ov.y;
                ((float*)&rlo)[j] = e + o;
                ((float*)&rhi)[j] = e - o;
            }
            float* row = obase + (size_t)(og + 16 * i) * 1024;
            *(float4*)(row + n0)       = rlo;
            *(float4*)(row + n0 + 512) = rhi;
        }
    }
}

// ============================================================================
extern "C" void kernel_launch(void* const* d_in, const int* in_sizes, int n_in,
                              void* d_out, int out_size)
{
    const float* q  = (const float*)d_in[0];
    const float* k  = (const float*)d_in[1];
    // d_in[2] = v : unused by the reference math
    const float* Wr = (const float*)d_in[3];
    const float* Wi = (const float*)d_in[4];
    float* out = (float*)d_out;

    k_dft  <<<dim3(BHN, 2), 256>>>(q, k);
    k_qk2  <<<BHN, 256>>>();
    k_w    <<<BHN * 2, 256>>>(Wr, Wi);
    k_irfft<<<BHN * 2, 256>>>(out);
}